// round 1
// baseline (speedup 1.0000x reference)
#include <cuda_runtime.h>

#define NROWS 32768
#define CCLS  2048
#define DDIM  512

#define BM 128
#define BN 128
#define BK 16

// scratch for per-class squared norms (no cudaMalloc allowed)
__device__ float g_m2[CCLS];

// ---------------------------------------------------------------------------
// Kernel 0: m2[c] = sum_d mu[c][d]^2
// ---------------------------------------------------------------------------
__global__ void k_m2(const float* __restrict__ mu) {
    const int c = blockIdx.x;
    const float* r = mu + (size_t)c * DDIM;
    float s = 0.f;
    for (int d = threadIdx.x; d < DDIM; d += 128) {
        float v = r[d];
        s = fmaf(v, v, s);
    }
    #pragma unroll
    for (int o = 16; o; o >>= 1) s += __shfl_xor_sync(0xffffffffu, s, o);
    __shared__ float sm[4];
    if ((threadIdx.x & 31) == 0) sm[threadIdx.x >> 5] = s;
    __syncthreads();
    if (threadIdx.x == 0) g_m2[c] = sm[0] + sm[1] + sm[2] + sm[3];
}

// ---------------------------------------------------------------------------
// Kernel 1: S[i][j] = 2 * (X[i] . MU[j]) - m2[j]   (scores, row-shifted by x2)
// Classic SGEMM: 128x128 tile, BK=16, 256 threads, 8x8 per-thread, double buffer.
// ---------------------------------------------------------------------------
__global__ __launch_bounds__(256, 2)
void k_gemm(const float* __restrict__ X, const float* __restrict__ MU,
            float* __restrict__ S) {
    __shared__ float As[2][BK][BM];
    __shared__ float Bs[2][BK][BN];

    const int tid = threadIdx.x;
    const int bm = blockIdx.y * BM;
    const int bn = blockIdx.x * BN;
    const int tx = tid & 15;       // 0..15  -> column group (8 cols)
    const int ty = tid >> 4;       // 0..15  -> row group (8 rows)
    const int lr = tid >> 2;       // 0..63  loader row
    const int lc = (tid & 3) << 2; // 0,4,8,12 loader col (float4)

    const float* xp = X  + (size_t)(bm + lr) * DDIM + lc;
    const float* bp = MU + (size_t)(bn + lr) * DDIM + lc;

    float acc[8][8];
    #pragma unroll
    for (int i = 0; i < 8; i++)
        #pragma unroll
        for (int j = 0; j < 8; j++) acc[i][j] = 0.f;

    // prologue: load k-tile 0
    float4 ra0 = *(const float4*)(xp);
    float4 ra1 = *(const float4*)(xp + (size_t)64 * DDIM);
    float4 rb0 = *(const float4*)(bp);
    float4 rb1 = *(const float4*)(bp + (size_t)64 * DDIM);

    As[0][lc+0][lr]    = ra0.x; As[0][lc+1][lr]    = ra0.y;
    As[0][lc+2][lr]    = ra0.z; As[0][lc+3][lr]    = ra0.w;
    As[0][lc+0][lr+64] = ra1.x; As[0][lc+1][lr+64] = ra1.y;
    As[0][lc+2][lr+64] = ra1.z; As[0][lc+3][lr+64] = ra1.w;
    Bs[0][lc+0][lr]    = rb0.x; Bs[0][lc+1][lr]    = rb0.y;
    Bs[0][lc+2][lr]    = rb0.z; Bs[0][lc+3][lr]    = rb0.w;
    Bs[0][lc+0][lr+64] = rb1.x; Bs[0][lc+1][lr+64] = rb1.y;
    Bs[0][lc+2][lr+64] = rb1.z; Bs[0][lc+3][lr+64] = rb1.w;
    __syncthreads();

    int buf = 0;
    for (int k0 = 0; k0 < DDIM; k0 += BK) {
        const bool more = (k0 + BK) < DDIM;
        if (more) {
            const float* xn = xp + k0 + BK;
            const float* bq = bp + k0 + BK;
            ra0 = *(const float4*)(xn);
            ra1 = *(const float4*)(xn + (size_t)64 * DDIM);
            rb0 = *(const float4*)(bq);
            rb1 = *(const float4*)(bq + (size_t)64 * DDIM);
        }

        #pragma unroll
        for (int kk = 0; kk < BK; kk++) {
            float4 a0 = *(const float4*)&As[buf][kk][ty * 8];
            float4 a1 = *(const float4*)&As[buf][kk][ty * 8 + 4];
            float4 b0 = *(const float4*)&Bs[buf][kk][tx * 8];
            float4 b1 = *(const float4*)&Bs[buf][kk][tx * 8 + 4];
            float a[8] = {a0.x, a0.y, a0.z, a0.w, a1.x, a1.y, a1.z, a1.w};
            float b[8] = {b0.x, b0.y, b0.z, b0.w, b1.x, b1.y, b1.z, b1.w};
            #pragma unroll
            for (int i = 0; i < 8; i++)
                #pragma unroll
                for (int j = 0; j < 8; j++)
                    acc[i][j] = fmaf(a[i], b[j], acc[i][j]);
        }

        if (more) {
            const int nb = buf ^ 1;
            As[nb][lc+0][lr]    = ra0.x; As[nb][lc+1][lr]    = ra0.y;
            As[nb][lc+2][lr]    = ra0.z; As[nb][lc+3][lr]    = ra0.w;
            As[nb][lc+0][lr+64] = ra1.x; As[nb][lc+1][lr+64] = ra1.y;
            As[nb][lc+2][lr+64] = ra1.z; As[nb][lc+3][lr+64] = ra1.w;
            Bs[nb][lc+0][lr]    = rb0.x; Bs[nb][lc+1][lr]    = rb0.y;
            Bs[nb][lc+2][lr]    = rb0.z; Bs[nb][lc+3][lr]    = rb0.w;
            Bs[nb][lc+0][lr+64] = rb1.x; Bs[nb][lc+1][lr+64] = rb1.y;
            Bs[nb][lc+2][lr+64] = rb1.z; Bs[nb][lc+3][lr+64] = rb1.w;
            __syncthreads();
            buf = nb;
        }
    }

    // epilogue: s = 2*dot - m2[col]
    float m2c[8];
    #pragma unroll
    for (int j = 0; j < 8; j++) m2c[j] = g_m2[bn + tx * 8 + j];

    #pragma unroll
    for (int i = 0; i < 8; i++) {
        float* op = S + (size_t)(bm + ty * 8 + i) * CCLS + bn + tx * 8;
        float4 o0, o1;
        o0.x = 2.f * acc[i][0] - m2c[0];
        o0.y = 2.f * acc[i][1] - m2c[1];
        o0.z = 2.f * acc[i][2] - m2c[2];
        o0.w = 2.f * acc[i][3] - m2c[3];
        o1.x = 2.f * acc[i][4] - m2c[4];
        o1.y = 2.f * acc[i][5] - m2c[5];
        o1.z = 2.f * acc[i][6] - m2c[6];
        o1.w = 2.f * acc[i][7] - m2c[7];
        *(float4*)op       = o0;
        *(float4*)(op + 4) = o1;
    }
}

// ---------------------------------------------------------------------------
// Kernel 2: per-row masked softmax, in place on S.
// mode: 0=min, 1=max, 2=sum
// ---------------------------------------------------------------------------
__device__ __forceinline__ float block_red(float v, int mode, float* sred, int tid) {
    #pragma unroll
    for (int o = 16; o; o >>= 1) {
        float t = __shfl_xor_sync(0xffffffffu, v, o);
        v = (mode == 0) ? fminf(v, t) : (mode == 1) ? fmaxf(v, t) : (v + t);
    }
    __syncthreads();                       // protect sred from previous use
    if ((tid & 31) == 0) sred[tid >> 5] = v;
    __syncthreads();
    float r;
    if (mode == 0) {
        r = fminf(fminf(fminf(sred[0], sred[1]), fminf(sred[2], sred[3])),
                  fminf(fminf(sred[4], sred[5]), fminf(sred[6], sred[7])));
    } else if (mode == 1) {
        r = fmaxf(fmaxf(fmaxf(sred[0], sred[1]), fmaxf(sred[2], sred[3])),
                  fmaxf(fmaxf(sred[4], sred[5]), fmaxf(sred[6], sred[7])));
    } else {
        r = ((sred[0] + sred[1]) + (sred[2] + sred[3])) +
            ((sred[4] + sred[5]) + (sred[6] + sred[7]));
    }
    return r;
}

__global__ __launch_bounds__(256)
void k_softmax(float* __restrict__ S, const float* __restrict__ cK) {
    __shared__ float sred[8];
    const int row = blockIdx.x;
    const int tid = threadIdx.x;
    float4* sp = (float4*)(S + (size_t)row * CCLS);
    const float4* cp = (const float4*)cK;

    float4 v0 = sp[tid];
    float4 v1 = sp[tid + 256];
    float4 c0 = cp[tid];
    float4 c1 = cp[tid + 256];

    // 1) row min over ALL columns (pre-mask)
    float mn = fminf(fminf(fminf(v0.x, v0.y), fminf(v0.z, v0.w)),
                     fminf(fminf(v1.x, v1.y), fminf(v1.z, v1.w)));
    mn = block_red(mn, 0, sred, tid);
    const float mval = mn - 1.f;

    // 2) mask unvisited classes (cK == 0)
    v0.x = (c0.x == 0.f) ? mval : v0.x;
    v0.y = (c0.y == 0.f) ? mval : v0.y;
    v0.z = (c0.z == 0.f) ? mval : v0.z;
    v0.w = (c0.w == 0.f) ? mval : v0.w;
    v1.x = (c1.x == 0.f) ? mval : v1.x;
    v1.y = (c1.y == 0.f) ? mval : v1.y;
    v1.z = (c1.z == 0.f) ? mval : v1.z;
    v1.w = (c1.w == 0.f) ? mval : v1.w;

    // 3) row max
    float mx = fmaxf(fmaxf(fmaxf(v0.x, v0.y), fmaxf(v0.z, v0.w)),
                     fmaxf(fmaxf(v1.x, v1.y), fmaxf(v1.z, v1.w)));
    mx = block_red(mx, 1, sred, tid);

    // 4) exp + sum
    float4 e0, e1;
    e0.x = expf(v0.x - mx); e0.y = expf(v0.y - mx);
    e0.z = expf(v0.z - mx); e0.w = expf(v0.w - mx);
    e1.x = expf(v1.x - mx); e1.y = expf(v1.y - mx);
    e1.z = expf(v1.z - mx); e1.w = expf(v1.w - mx);
    float sum = ((e0.x + e0.y) + (e0.z + e0.w)) + ((e1.x + e1.y) + (e1.z + e1.w));
    sum = block_red(sum, 2, sred, tid);
    const float inv = 1.f / sum;

    // 5) normalize + write
    e0.x *= inv; e0.y *= inv; e0.z *= inv; e0.w *= inv;
    e1.x *= inv; e1.y *= inv; e1.z *= inv; e1.w *= inv;
    sp[tid]       = e0;
    sp[tid + 256] = e1;
}

// ---------------------------------------------------------------------------
extern "C" void kernel_launch(void* const* d_in, const int* in_sizes, int n_in,
                              void* d_out, int out_size) {
    const float* X  = (const float*)d_in[0];   // (N, D) fp32
    const float* MU = (const float*)d_in[1];   // (C, D) fp32
    const float* cK = (const float*)d_in[2];   // (C,)   fp32
    float* out = (float*)d_out;                // (N, C) fp32

    k_m2<<<CCLS, 128>>>(MU);

    dim3 grid(CCLS / BN, NROWS / BM);          // (16, 256)
    k_gemm<<<grid, 256>>>(X, MU, out);

    k_softmax<<<NROWS, 256>>>(out, cK);
}